// round 9
// baseline (speedup 1.0000x reference)
#include <cuda_runtime.h>
#include <cuda_fp16.h>
#include <cstdint>

// ColumnParallelLinear: C[8192,4096] = A[8192,1024] @ W[4096,1024]^T (fp32).
// Single-term fp16 HMMA GEMM (norm rel-err ~3e-4 < 1e-3 threshold).
// CTA tile 128x256, 8 warps (2Mx4N), warp tile 64x64 (halved LDSM/MMA ratio),
// 4-stage cp.async pipeline (48KB/stage), SW128 swizzle, 1 CTA/SM, 255 regs.

#define M_DIM 8192
#define N_DIM 4096
#define K_DIM 1024

#define BM 128
#define BN 256
#define BK 64                     // fp16 per k-chunk: 64*2 = 128B rows (SW128)
#define STAGES 4
#define KSTEPS (K_DIM / BK)       // 16

#define OFF_A 0                   // A tile: 128 rows * 128B = 16KB
#define OFF_W 16384               // W tile: 256 rows * 128B = 32KB
#define STAGE_B 49152
#define SMEM_TOTAL (STAGES * STAGE_B)   // 196608

// ---------------- scratch (device globals: allocation-free rule) -------------
__device__ __half g_Ah[M_DIM * K_DIM];
__device__ __half g_Wh[N_DIM * K_DIM];

// ---------------- PTX helpers (compute_103-legal) ----------------------------
__device__ __forceinline__ uint32_t smem_u32(const void* p) {
    uint32_t a;
    asm("{ .reg .u64 t; cvta.to.shared.u64 t, %1; cvt.u32.u64 %0, t; }"
        : "=r"(a) : "l"(p));
    return a;
}
__device__ __forceinline__ void cp16(uint32_t dst, const void* src) {
    asm volatile("cp.async.cg.shared.global [%0], [%1], 16;"
                 :: "r"(dst), "l"(src) : "memory");
}
__device__ __forceinline__ void cp_commit() {
    asm volatile("cp.async.commit_group;" ::: "memory");
}
template <int N>
__device__ __forceinline__ void cp_wait() {
    asm volatile("cp.async.wait_group %0;" :: "n"(N) : "memory");
}
__device__ __forceinline__ void ldsm4(uint32_t* r, uint32_t addr) {
    asm volatile("ldmatrix.sync.aligned.m8n8.x4.shared.b16 {%0,%1,%2,%3}, [%4];"
                 : "=r"(r[0]), "=r"(r[1]), "=r"(r[2]), "=r"(r[3]) : "r"(addr));
}
__device__ __forceinline__ void mma_f16(float* d, const uint32_t* a,
                                        const uint32_t* b) {
    asm volatile(
        "mma.sync.aligned.m16n8k16.row.col.f32.f16.f16.f32 "
        "{%0,%1,%2,%3}, {%4,%5,%6,%7}, {%8,%9}, {%0,%1,%2,%3};"
        : "+f"(d[0]), "+f"(d[1]), "+f"(d[2]), "+f"(d[3])
        : "r"(a[0]), "r"(a[1]), "r"(a[2]), "r"(a[3]), "r"(b[0]), "r"(b[1]));
}

// ---------------- fused convert kernel: fp32 -> fp16 (A then W) --------------
__global__ void cvt_fused_kernel(const float* __restrict__ A,
                                 const float* __restrict__ W) {
    const int n8a = (M_DIM * K_DIM) / 8;
    int i = blockIdx.x * blockDim.x + threadIdx.x;
    const float* src;
    __half* dst;
    if (i < n8a) {
        src = A; dst = g_Ah;
    } else {
        src = W; dst = g_Wh; i -= n8a;
    }
    float4 v0 = reinterpret_cast<const float4*>(src)[2 * i];
    float4 v1 = reinterpret_cast<const float4*>(src)[2 * i + 1];
    __half2 h[4];
    h[0] = __floats2half2_rn(v0.x, v0.y);
    h[1] = __floats2half2_rn(v0.z, v0.w);
    h[2] = __floats2half2_rn(v1.x, v1.y);
    h[3] = __floats2half2_rn(v1.z, v1.w);
    reinterpret_cast<float4*>(dst)[i] = *reinterpret_cast<float4*>(h);
}

// ---------------- GEMM kernel ------------------------------------------------
__global__ __launch_bounds__(256, 1)
void gemm_f16_kernel(float* __restrict__ C) {
    extern __shared__ char smem[];
    const uint32_t sb = smem_u32(smem);
    const int tid  = threadIdx.x;
    const int wid  = tid >> 5;
    const int lane = tid & 31;
    const int bm = blockIdx.y * BM;
    const int bn = blockIdx.x * BN;
    const int mw = (wid & 1) * 64;    // warp M offset (2 warps along M)
    const int nw = (wid >> 1) * 64;   // warp N offset (4 warps along N, 64 wide)

    // ---- cp.async staging geometry (16B chunks; 128B rows) ------------------
    // A: 128 rows -> 4 chunks/thread;  W: 256 rows -> 8 chunks/thread.
    const int crow = tid >> 3;        // 0..31
    const int cc16 = tid & 7;         // 16B chunk within row
    uint32_t dswA[4], dswW[8];
#pragma unroll
    for (int i = 0; i < 4; i++) {
        uint32_t off = (uint32_t)(crow + i * 32) * 128 + (uint32_t)cc16 * 16;
        dswA[i] = off ^ ((off >> 3) & 0x70);
    }
#pragma unroll
    for (int i = 0; i < 8; i++) {
        uint32_t off = (uint32_t)(crow + i * 32) * 128 + (uint32_t)cc16 * 16;
        dswW[i] = off ^ ((off >> 3) & 0x70);
    }
    const __half* srcA = g_Ah + (size_t)(bm + crow) * K_DIM + cc16 * 8;
    const __half* srcW = g_Wh + (size_t)(bn + crow) * K_DIM + cc16 * 8;

    auto load_stage = [&](uint32_t b, int kc) {
        size_t ko = (size_t)kc * BK;
#pragma unroll
        for (int i = 0; i < 4; i++)
            cp16(b + OFF_A + dswA[i], srcA + (size_t)i * 32 * K_DIM + ko);
#pragma unroll
        for (int i = 0; i < 8; i++)
            cp16(b + OFF_W + dswW[i], srcW + (size_t)i * 32 * K_DIM + ko);
        cp_commit();
    };

    // ---- ldmatrix address precompute ---------------------------------------
    const uint32_t aK   = (uint32_t)(lane >> 4) * 16;
    const uint32_t xorA = (uint32_t)(lane & 7) << 4;
    uint32_t rowA[4];
#pragma unroll
    for (int mi = 0; mi < 4; mi++)
        rowA[mi] = (uint32_t)(mw + mi * 16 + (lane & 15)) * 128;
    const uint32_t bK   = (uint32_t)((lane >> 3) & 1) << 4;
    const uint32_t xorB = (uint32_t)(lane & 7) << 4;
    uint32_t rowB[4];
#pragma unroll
    for (int nb = 0; nb < 4; nb++)
        rowB[nb] = (uint32_t)(nw + nb * 16 + ((lane >> 4) << 3) + (lane & 7)) * 128;

    float acc[4][8][4];
#pragma unroll
    for (int mi = 0; mi < 4; mi++)
#pragma unroll
        for (int ni = 0; ni < 8; ni++)
#pragma unroll
            for (int q = 0; q < 4; q++) acc[mi][ni][q] = 0.0f;

    // ---- pipeline prologue: stage 3 chunks ----------------------------------
    load_stage(sb, 0);
    load_stage(sb + STAGE_B, 1);
    load_stage(sb + 2u * STAGE_B, 2);

    uint32_t cbase = sb;                      // compute stage
    uint32_t lbase = sb + 3u * STAGE_B;       // next load stage
    const uint32_t wrap = sb + (uint32_t)STAGES * STAGE_B;

    // ---- mainloop: one barrier per k-chunk ----------------------------------
    for (int kc = 0; kc < KSTEPS; kc++) {
        if (kc < KSTEPS - 1) cp_wait<2>(); else cp_wait<0>();
        __syncthreads();

        if (kc + 3 < KSTEPS) {
            load_stage(lbase, kc + 3);
            lbase += STAGE_B; if (lbase == wrap) lbase = sb;
        }

#pragma unroll
        for (int kk = 0; kk < 4; kk++) {
            const uint32_t colA = (uint32_t)(kk * 32 + aK) ^ xorA;
            const uint32_t colB = (uint32_t)(kk * 32 + bK) ^ xorB;
            uint32_t af[4][4], bf[4][4];
#pragma unroll
            for (int mi = 0; mi < 4; mi++)
                ldsm4(af[mi], cbase + OFF_A + rowA[mi] + colA);
#pragma unroll
            for (int nb = 0; nb < 4; nb++)
                ldsm4(bf[nb], cbase + OFF_W + rowB[nb] + colB);
#pragma unroll
            for (int mi = 0; mi < 4; mi++) {
#pragma unroll
                for (int ni = 0; ni < 8; ni++) {
                    mma_f16(acc[mi][ni], af[mi], &bf[ni >> 1][(ni & 1) * 2]);
                }
            }
        }
        cbase += STAGE_B; if (cbase == wrap) cbase = sb;
    }

    // ---- epilogue: registers -> C (float4 stores over adjacent n8 frags) ----
    const int er = lane >> 2;           // 0..7
    const int ec = (lane & 3) * 2;      // 0,2,4,6
#pragma unroll
    for (int mi = 0; mi < 4; mi++) {
#pragma unroll
        for (int ni = 0; ni < 8; ni += 2) {
            const int m = bm + mw + mi * 16 + er;
            const int n = bn + nw + ni * 8 + ec;
            float* r0 = C + (size_t)m * N_DIM + n;
            float* r1 = C + (size_t)(m + 8) * N_DIM + n;
            float2 a0 = {acc[mi][ni][0],     acc[mi][ni][1]};
            float2 b0 = {acc[mi][ni + 1][0], acc[mi][ni + 1][1]};
            float2 a1 = {acc[mi][ni][2],     acc[mi][ni][3]};
            float2 b1 = {acc[mi][ni + 1][2], acc[mi][ni + 1][3]};
            *reinterpret_cast<float2*>(r0)     = a0;
            *reinterpret_cast<float2*>(r0 + 8) = b0;
            *reinterpret_cast<float2*>(r1)     = a1;
            *reinterpret_cast<float2*>(r1 + 8) = b1;
        }
    }
}

// ---------------- host launch ------------------------------------------------
extern "C" void kernel_launch(void* const* d_in, const int* in_sizes, int n_in,
                              void* d_out, int out_size) {
    const float* A = (const float*)d_in[0];   // [8192, 1024]
    const float* W = (const float*)d_in[1];   // [4096, 1024]
    float* C       = (float*)d_out;           // [8192, 4096]

    {
        const int n8 = (M_DIM * K_DIM + N_DIM * K_DIM) / 8;
        cvt_fused_kernel<<<n8 / 256, 256>>>(A, W);
    }

    cudaFuncSetAttribute(gemm_f16_kernel,
                         cudaFuncAttributeMaxDynamicSharedMemorySize, SMEM_TOTAL);
    dim3 grid(N_DIM / BN, M_DIM / BM);   // (16, 64)
    gemm_f16_kernel<<<grid, 256, SMEM_TOTAL>>>(C);
}

// round 10
// speedup vs baseline: 1.1229x; 1.1229x over previous
#include <cuda_runtime.h>
#include <cuda_fp16.h>
#include <cstdint>

// ColumnParallelLinear: C[8192,4096] = A[8192,1024] @ W[4096,1024]^T (fp32).
// Single-term fp16 HMMA GEMM (norm rel-err ~3e-4 < 1e-3 threshold).
// CTA tile 128x128 with 4 warps (2Mx2N, warp tile 64x64): keeps the low
// 0.25 LDSM/MMA ratio of R9 while restoring 2 CTAs/SM occupancy (16 warps/SM).
// 3-stage cp.async pipeline (32KB/stage), SW128 swizzle.

#define M_DIM 8192
#define N_DIM 4096
#define K_DIM 1024

#define BM 128
#define BN 128
#define BK 64                     // fp16 per k-chunk: 64*2 = 128B rows (SW128)
#define STAGES 3
#define KSTEPS (K_DIM / BK)       // 16

#define OFF_A 0                   // A tile: 128 rows * 128B = 16KB
#define OFF_W 16384               // W tile: 128 rows * 128B = 16KB
#define STAGE_B 32768
#define SMEM_TOTAL (STAGES * STAGE_B)   // 98304 per CTA

// ---------------- scratch (device globals: allocation-free rule) -------------
__device__ __half g_Ah[M_DIM * K_DIM];
__device__ __half g_Wh[N_DIM * K_DIM];

// ---------------- PTX helpers (compute_103-legal) ----------------------------
__device__ __forceinline__ uint32_t smem_u32(const void* p) {
    uint32_t a;
    asm("{ .reg .u64 t; cvta.to.shared.u64 t, %1; cvt.u32.u64 %0, t; }"
        : "=r"(a) : "l"(p));
    return a;
}
__device__ __forceinline__ void cp16(uint32_t dst, const void* src) {
    asm volatile("cp.async.cg.shared.global [%0], [%1], 16;"
                 :: "r"(dst), "l"(src) : "memory");
}
__device__ __forceinline__ void cp_commit() {
    asm volatile("cp.async.commit_group;" ::: "memory");
}
template <int N>
__device__ __forceinline__ void cp_wait() {
    asm volatile("cp.async.wait_group %0;" :: "n"(N) : "memory");
}
__device__ __forceinline__ void ldsm4(uint32_t* r, uint32_t addr) {
    asm volatile("ldmatrix.sync.aligned.m8n8.x4.shared.b16 {%0,%1,%2,%3}, [%4];"
                 : "=r"(r[0]), "=r"(r[1]), "=r"(r[2]), "=r"(r[3]) : "r"(addr));
}
__device__ __forceinline__ void mma_f16(float* d, const uint32_t* a,
                                        const uint32_t* b) {
    asm volatile(
        "mma.sync.aligned.m16n8k16.row.col.f32.f16.f16.f32 "
        "{%0,%1,%2,%3}, {%4,%5,%6,%7}, {%8,%9}, {%0,%1,%2,%3};"
        : "+f"(d[0]), "+f"(d[1]), "+f"(d[2]), "+f"(d[3])
        : "r"(a[0]), "r"(a[1]), "r"(a[2]), "r"(a[3]), "r"(b[0]), "r"(b[1]));
}

// ---------------- fused convert kernel: fp32 -> fp16 (A then W) --------------
__global__ void cvt_fused_kernel(const float* __restrict__ A,
                                 const float* __restrict__ W) {
    const int n8a = (M_DIM * K_DIM) / 8;
    int i = blockIdx.x * blockDim.x + threadIdx.x;
    const float* src;
    __half* dst;
    if (i < n8a) {
        src = A; dst = g_Ah;
    } else {
        src = W; dst = g_Wh; i -= n8a;
    }
    float4 v0 = reinterpret_cast<const float4*>(src)[2 * i];
    float4 v1 = reinterpret_cast<const float4*>(src)[2 * i + 1];
    __half2 h[4];
    h[0] = __floats2half2_rn(v0.x, v0.y);
    h[1] = __floats2half2_rn(v0.z, v0.w);
    h[2] = __floats2half2_rn(v1.x, v1.y);
    h[3] = __floats2half2_rn(v1.z, v1.w);
    reinterpret_cast<float4*>(dst)[i] = *reinterpret_cast<float4*>(h);
}

// ---------------- GEMM kernel ------------------------------------------------
__global__ __launch_bounds__(128, 2)
void gemm_f16_kernel(float* __restrict__ C) {
    extern __shared__ char smem[];
    const uint32_t sb = smem_u32(smem);
    const int tid  = threadIdx.x;
    const int wid  = tid >> 5;        // 0..3
    const int lane = tid & 31;
    const int bm = blockIdx.y * BM;
    const int bn = blockIdx.x * BN;
    const int mw = (wid & 1) * 64;    // warp M offset (2 warps along M)
    const int nw = (wid >> 1) * 64;   // warp N offset (2 warps along N, 64 wide)

    // ---- cp.async staging geometry (16B chunks; 128B rows) ------------------
    // 128 threads: A 128 rows -> 8 chunks/thread; W 128 rows -> 8 chunks/thread.
    const int crow = tid >> 3;        // 0..15 (base row; +16*i covers 128 rows)
    const int cc16 = tid & 7;         // 16B chunk within row
    uint32_t dsw[8];
#pragma unroll
    for (int i = 0; i < 8; i++) {
        uint32_t off = (uint32_t)(crow + i * 16) * 128 + (uint32_t)cc16 * 16;
        dsw[i] = off ^ ((off >> 3) & 0x70);
    }
    const __half* srcA = g_Ah + (size_t)(bm + crow) * K_DIM + cc16 * 8;
    const __half* srcW = g_Wh + (size_t)(bn + crow) * K_DIM + cc16 * 8;

    auto load_stage = [&](uint32_t b, int kc) {
        size_t ko = (size_t)kc * BK;
#pragma unroll
        for (int i = 0; i < 8; i++) {
            size_t ro = (size_t)i * 16 * K_DIM + ko;
            cp16(b + OFF_A + dsw[i], srcA + ro);
            cp16(b + OFF_W + dsw[i], srcW + ro);
        }
        cp_commit();
    };

    // ---- ldmatrix address precompute ---------------------------------------
    const uint32_t aK   = (uint32_t)(lane >> 4) * 16;
    const uint32_t xorA = (uint32_t)(lane & 7) << 4;
    uint32_t rowA[4];
#pragma unroll
    for (int mi = 0; mi < 4; mi++)
        rowA[mi] = (uint32_t)(mw + mi * 16 + (lane & 15)) * 128;
    const uint32_t bK   = (uint32_t)((lane >> 3) & 1) << 4;
    const uint32_t xorB = (uint32_t)(lane & 7) << 4;
    uint32_t rowB[4];
#pragma unroll
    for (int nb = 0; nb < 4; nb++)
        rowB[nb] = (uint32_t)(nw + nb * 16 + ((lane >> 4) << 3) + (lane & 7)) * 128;

    float acc[4][8][4];
#pragma unroll
    for (int mi = 0; mi < 4; mi++)
#pragma unroll
        for (int ni = 0; ni < 8; ni++)
#pragma unroll
            for (int q = 0; q < 4; q++) acc[mi][ni][q] = 0.0f;

    // ---- pipeline prologue --------------------------------------------------
    load_stage(sb, 0);
    load_stage(sb + STAGE_B, 1);

    uint32_t cbase = sb;                      // compute stage
    uint32_t lbase = sb + 2u * STAGE_B;       // next load stage
    const uint32_t wrap = sb + (uint32_t)STAGES * STAGE_B;

    // ---- mainloop: one barrier per k-chunk ----------------------------------
    for (int kc = 0; kc < KSTEPS; kc++) {
        if (kc < KSTEPS - 1) cp_wait<1>(); else cp_wait<0>();
        __syncthreads();

        if (kc + 2 < KSTEPS) {
            load_stage(lbase, kc + 2);
            lbase += STAGE_B; if (lbase == wrap) lbase = sb;
        }

#pragma unroll
        for (int kk = 0; kk < 4; kk++) {
            const uint32_t colA = (uint32_t)(kk * 32 + aK) ^ xorA;
            const uint32_t colB = (uint32_t)(kk * 32 + bK) ^ xorB;
            uint32_t af[4][4], bf[4][4];
#pragma unroll
            for (int mi = 0; mi < 4; mi++)
                ldsm4(af[mi], cbase + OFF_A + rowA[mi] + colA);
#pragma unroll
            for (int nb = 0; nb < 4; nb++)
                ldsm4(bf[nb], cbase + OFF_W + rowB[nb] + colB);
#pragma unroll
            for (int mi = 0; mi < 4; mi++) {
#pragma unroll
                for (int ni = 0; ni < 8; ni++) {
                    mma_f16(acc[mi][ni], af[mi], &bf[ni >> 1][(ni & 1) * 2]);
                }
            }
        }
        cbase += STAGE_B; if (cbase == wrap) cbase = sb;
    }

    // ---- epilogue: registers -> C ------------------------------------------
    const int er = lane >> 2;           // 0..7
    const int ec = (lane & 3) * 2;      // 0,2,4,6
#pragma unroll
    for (int mi = 0; mi < 4; mi++) {
#pragma unroll
        for (int ni = 0; ni < 8; ni += 2) {
            const int m = bm + mw + mi * 16 + er;
            const int n = bn + nw + ni * 8 + ec;
            float* r0 = C + (size_t)m * N_DIM + n;
            float* r1 = C + (size_t)(m + 8) * N_DIM + n;
            float2 a0 = {acc[mi][ni][0],     acc[mi][ni][1]};
            float2 b0 = {acc[mi][ni + 1][0], acc[mi][ni + 1][1]};
            float2 a1 = {acc[mi][ni][2],     acc[mi][ni][3]};
            float2 b1 = {acc[mi][ni + 1][2], acc[mi][ni + 1][3]};
            *reinterpret_cast<float2*>(r0)     = a0;
            *reinterpret_cast<float2*>(r0 + 8) = b0;
            *reinterpret_cast<float2*>(r1)     = a1;
            *reinterpret_cast<float2*>(r1 + 8) = b1;
        }
    }
}

// ---------------- host launch ------------------------------------------------
extern "C" void kernel_launch(void* const* d_in, const int* in_sizes, int n_in,
                              void* d_out, int out_size) {
    const float* A = (const float*)d_in[0];   // [8192, 1024]
    const float* W = (const float*)d_in[1];   // [4096, 1024]
    float* C       = (float*)d_out;           // [8192, 4096]

    {
        const int n8 = (M_DIM * K_DIM + N_DIM * K_DIM) / 8;
        cvt_fused_kernel<<<n8 / 256, 256>>>(A, W);
    }

    cudaFuncSetAttribute(gemm_f16_kernel,
                         cudaFuncAttributeMaxDynamicSharedMemorySize, SMEM_TOTAL);
    dim3 grid(N_DIM / BN, M_DIM / BM);   // (32, 64)
    gemm_f16_kernel<<<grid, 128, SMEM_TOTAL>>>(C);
}